// round 3
// baseline (speedup 1.0000x reference)
#include <cuda_runtime.h>
#include <cuda_bf16.h>

// LengthRegulator:
//   x:        (B=32, C=384, T=1024) float32
//   duration: (B, T) int32  (JAX x64 disabled: astype(int64) yields int32)
//   max_len:  8192 (scalar input, ignored; shapes hardcoded)
// Output 0: out (B, C+2, ML) float32
// Output 1: mel_len (B,) — stored as FLOAT32 VALUES at the tail of d_out
//           (harness keeps one f32 buffer; R2 proved int-bit writes read as ~0)
//
// k1: per-batch scan of clipped durations, scatter pos->token map, tail fill,
//     mel_len write.
// k2: streaming expand: smem-staged chunk of (tok, idx_in, len), then 96
//     channel rows per block with float4 coalesced stores + gathered x loads.

#define LR_B   32
#define LR_C   384
#define LR_T   1024
#define LR_ML  8192
#define LR_MAXDUR 10000
#define LR_PCH 1024   // positions per chunk
#define LR_CPG 96     // channels per c-group (384/4)

__device__ int g_tok[LR_B * LR_ML];     // token index per output position, -1 = invalid
__device__ int g_start[LR_B * LR_T];    // start position of each token
__device__ int g_dur[LR_B * LR_T];      // clipped duration of each token

__global__ __launch_bounds__(1024) void lr_scan_scatter_kernel(
    const int* __restrict__ duration,
    float* __restrict__ out,
    long long out_size)
{
    const int b = blockIdx.x;
    const int t = threadIdx.x;

    int dv = duration[b * LR_T + t];
    if (dv < 0) dv = -dv;
    int d = dv < 1 ? 1 : (dv > LR_MAXDUR ? LR_MAXDUR : dv);

    // Block-wide inclusive scan (Hillis-Steele, 1024 threads)
    __shared__ int s[LR_T];
    s[t] = d;
    __syncthreads();
    #pragma unroll
    for (int off = 1; off < LR_T; off <<= 1) {
        int v = (t >= off) ? s[t - off] : 0;
        __syncthreads();
        s[t] += v;
        __syncthreads();
    }
    const int end   = s[t];
    const int start = end - d;

    g_start[b * LR_T + t] = start;
    g_dur  [b * LR_T + t] = d;

    __shared__ int s_total;
    if (t == LR_T - 1) {
        s_total = end;
        // mel_len appended after the main output tensor, as float32 VALUES
        long long main_elems = (long long)LR_B * (LR_C + 2) * LR_ML;
        if (out_size >= main_elems + LR_B) {
            out[main_elems + b] = (float)end;
        }
    }
    __syncthreads();

    // Scatter: positions [start, end) belong to token t
    int* tokb = g_tok + (size_t)b * LR_ML;
    for (int pos = start; pos < end && pos < LR_ML; ++pos) {
        tokb[pos] = t;
    }
    // Tail fill: positions >= total are invalid
    const int total = s_total;
    for (int pos = total + t; pos < LR_ML; pos += LR_T) {
        tokb[pos] = -1;
    }
}

__global__ __launch_bounds__(256) void lr_expand_kernel(
    const float* __restrict__ x,
    float* __restrict__ out)
{
    const int chunk = blockIdx.x;   // 0..7
    const int b     = blockIdx.y;   // 0..31
    const int cg    = blockIdx.z;   // 0..3
    const int p0    = chunk * LR_PCH;

    __shared__ int   s_tok[LR_PCH];
    __shared__ float s_idx[LR_PCH];
    __shared__ float s_len[LR_PCH];

    // Stage chunk metadata
    for (int i = threadIdx.x; i < LR_PCH; i += 256) {
        int tk = g_tok[(size_t)b * LR_ML + p0 + i];
        s_tok[i] = tk;
        float fi = 0.0f, fl = 0.0f;
        if (tk >= 0) {
            fi = (float)(p0 + i - g_start[b * LR_T + tk]);
            fl = (float)g_dur[b * LR_T + tk];
        }
        s_idx[i] = fi;
        s_len[i] = fl;
    }
    __syncthreads();

    const int base = threadIdx.x * 4;
    const int t0 = s_tok[base + 0];
    const int t1 = s_tok[base + 1];
    const int t2 = s_tok[base + 2];
    const int t3 = s_tok[base + 3];

    const float* xb = x + (size_t)b * LR_C * LR_T;
    float* ob = out + (size_t)b * (LR_C + 2) * LR_ML + p0 + base;

    const int c0 = cg * LR_CPG;
    #pragma unroll 2
    for (int c = c0; c < c0 + LR_CPG; ++c) {
        const float* xr = xb + (size_t)c * LR_T;
        float4 v;
        v.x = (t0 >= 0) ? __ldg(xr + t0) : 0.0f;
        v.y = (t1 >= 0) ? __ldg(xr + t1) : 0.0f;
        v.z = (t2 >= 0) ? __ldg(xr + t2) : 0.0f;
        v.w = (t3 >= 0) ? __ldg(xr + t3) : 0.0f;
        *reinterpret_cast<float4*>(ob + (size_t)c * LR_ML) = v;
    }

    // c-group 3 also emits the idx_in and length rows
    if (cg == 3) {
        float4 vi = *reinterpret_cast<const float4*>(&s_idx[base]);
        float4 vl = *reinterpret_cast<const float4*>(&s_len[base]);
        *reinterpret_cast<float4*>(ob + (size_t)LR_C       * LR_ML) = vi;
        *reinterpret_cast<float4*>(ob + (size_t)(LR_C + 1) * LR_ML) = vl;
    }
}

extern "C" void kernel_launch(void* const* d_in, const int* in_sizes, int n_in,
                              void* d_out, int out_size)
{
    const float* x   = (const float*)d_in[0];
    const int*   dur = (const int*)d_in[1];
    float*       out = (float*)d_out;

    lr_scan_scatter_kernel<<<LR_B, 1024>>>(dur, out, (long long)out_size);

    dim3 grid(LR_ML / LR_PCH, LR_B, 4);
    lr_expand_kernel<<<grid, 256>>>(x, out);
}

// round 6
// speedup vs baseline: 1.0656x; 1.0656x over previous
#include <cuda_runtime.h>
#include <cuda_bf16.h>

// LengthRegulator, fused single kernel.
//   x:        (B=32, C=384, T=1024) float32
//   duration: (B, T) int32
// Output 0: out (B, C+2, ML=8192) float32
// Output 1: mel_len (B,) as float32 values at tail of d_out
//
// Per block (chunk, b, cg): re-scan durations (4KB, L2-resident) with a
// shuffle block scan, branchless searchsorted for this thread's 4 positions
// (1 binary search + 3 incremental steps; dur>=1 => tok increments <=1),
// then stream 96 channel rows with float4 stores, channel loop unrolled x4
// for 16 gathered loads + 4 stores in flight.

#define LR_B   32
#define LR_C   384
#define LR_T   1024
#define LR_ML  8192
#define LR_MAXDUR 10000
#define LR_PCH 1024   // positions per chunk
#define LR_CPG 96     // channels per c-group (384/4)

__device__ __forceinline__ int lr_clip(int v) {
    v = v < 0 ? -v : v;
    return v < 1 ? 1 : (v > LR_MAXDUR ? LR_MAXDUR : v);
}

__global__ __launch_bounds__(256) void lr_fused_kernel(
    const float* __restrict__ x,
    const int* __restrict__ duration,
    float* __restrict__ out,
    long long out_size)
{
    const int chunk = blockIdx.x;   // 0..7
    const int b     = blockIdx.y;   // 0..31
    const int cg    = blockIdx.z;   // 0..3
    const int tid   = threadIdx.x;
    const int lane  = tid & 31;
    const int wrp   = tid >> 5;

    __shared__ int s_end[LR_T + 1]; // inclusive cumsum of clipped durations + sentinel
    __shared__ int s_wsum[8];

    // ---- load 4 durations (16B vectorized), clip, local cumsums ----
    int4 dv = *reinterpret_cast<const int4*>(duration + b * LR_T + tid * 4);
    int d0 = lr_clip(dv.x);
    int d1 = lr_clip(dv.y);
    int d2 = lr_clip(dv.z);
    int d3 = lr_clip(dv.w);
    int c0 = d0, c1 = c0 + d1, c2 = c1 + d2, c3 = c2 + d3;

    // ---- warp inclusive scan of per-thread sums ----
    int v = c3;
    #pragma unroll
    for (int off = 1; off < 32; off <<= 1) {
        int n = __shfl_up_sync(0xffffffffu, v, off);
        if (lane >= off) v += n;
    }
    int wexcl = v - c3;               // exclusive prefix within warp
    if (lane == 31) s_wsum[wrp] = v;  // warp total
    __syncthreads();
    if (tid == 0) {
        int acc = 0;
        #pragma unroll
        for (int i = 0; i < 8; ++i) { int t = s_wsum[i]; s_wsum[i] = acc; acc += t; }
        s_end[LR_T] = 0x7fffffff;     // sentinel for incremental search
    }
    __syncthreads();
    const int base = s_wsum[wrp] + wexcl;
    s_end[tid * 4 + 0] = base + c0;
    s_end[tid * 4 + 1] = base + c1;
    s_end[tid * 4 + 2] = base + c2;
    s_end[tid * 4 + 3] = base + c3;
    __syncthreads();

    const int total = s_end[LR_T - 1];

    // mel_len (float values) from one block per batch
    if (chunk == 0 && cg == 0 && tid == 0) {
        long long main_elems = (long long)LR_B * (LR_C + 2) * LR_ML;
        if (out_size >= main_elems + LR_B) out[main_elems + b] = (float)total;
    }

    // ---- searchsorted(right) for 4 consecutive positions ----
    const int p0   = chunk * LR_PCH;
    const int pos0 = p0 + tid * 4;

    int lo = 0;  // count of ends <= pos0
    #pragma unroll
    for (int step = 512; step > 0; step >>= 1)
        if (s_end[lo + step - 1] <= pos0) lo += step;
    int t0 = lo;
    int t1 = t0 + (s_end[t0] <= pos0 + 1);
    int t2 = t1 + (s_end[t1] <= pos0 + 2);
    int t3 = t2 + (s_end[t2] <= pos0 + 3);

    const bool v0 = pos0     < total;
    const bool v1 = pos0 + 1 < total;
    const bool v2 = pos0 + 2 < total;
    const bool v3 = pos0 + 3 < total;

    // idx_in / length (only stored by cg==3, cheap to compute)
    float fi0 = 0.f, fi1 = 0.f, fi2 = 0.f, fi3 = 0.f;
    float fl0 = 0.f, fl1 = 0.f, fl2 = 0.f, fl3 = 0.f;
    if (v0) { int pv = t0 ? s_end[t0 - 1] : 0; fi0 = (float)(pos0     - pv); fl0 = (float)(s_end[t0] - pv); }
    if (v1) { int pv = t1 ? s_end[t1 - 1] : 0; fi1 = (float)(pos0 + 1 - pv); fl1 = (float)(s_end[t1] - pv); }
    if (v2) { int pv = t2 ? s_end[t2 - 1] : 0; fi2 = (float)(pos0 + 2 - pv); fl2 = (float)(s_end[t2] - pv); }
    if (v3) { int pv = t3 ? s_end[t3 - 1] : 0; fi3 = (float)(pos0 + 3 - pv); fl3 = (float)(s_end[t3] - pv); }

    // final token indices (-1 = invalid/zero)
    t0 = v0 ? t0 : -1;
    t1 = v1 ? t1 : -1;
    t2 = v2 ? t2 : -1;
    t3 = v3 ? t3 : -1;

    // ---- channel streaming: 96 rows, unroll x4 for MLP ----
    const float* xb = x + (size_t)b * LR_C * LR_T;
    float* ob = out + (size_t)b * (LR_C + 2) * LR_ML + pos0;

    const int cbase = cg * LR_CPG;
    #pragma unroll 4
    for (int c = cbase; c < cbase + LR_CPG; ++c) {
        const float* xr = xb + (size_t)c * LR_T;
        float4 w;
        w.x = (t0 >= 0) ? __ldg(xr + t0) : 0.0f;
        w.y = (t1 >= 0) ? __ldg(xr + t1) : 0.0f;
        w.z = (t2 >= 0) ? __ldg(xr + t2) : 0.0f;
        w.w = (t3 >= 0) ? __ldg(xr + t3) : 0.0f;
        *reinterpret_cast<float4*>(ob + (size_t)c * LR_ML) = w;
    }

    // c-group 3 also emits the idx_in and length rows
    if (cg == 3) {
        float4 vi = make_float4(fi0, fi1, fi2, fi3);
        float4 vl = make_float4(fl0, fl1, fl2, fl3);
        *reinterpret_cast<float4*>(ob + (size_t)LR_C       * LR_ML) = vi;
        *reinterpret_cast<float4*>(ob + (size_t)(LR_C + 1) * LR_ML) = vl;
    }
}

extern "C" void kernel_launch(void* const* d_in, const int* in_sizes, int n_in,
                              void* d_out, int out_size)
{
    const float* x   = (const float*)d_in[0];
    const int*   dur = (const int*)d_in[1];
    float*       out = (float*)d_out;

    dim3 grid(LR_ML / LR_PCH, LR_B, 4);
    lr_fused_kernel<<<grid, 256>>>(x, dur, out, (long long)out_size);
}